// round 9
// baseline (speedup 1.0000x reference)
#include <cuda_runtime.h>
#include <math.h>

// Spiking CNN forward, B=4096.

#define NB 4096
typedef unsigned long long u64;
typedef unsigned int uint32;

__device__ float g_Z[NB * 980];          // binary conv-stack output [m][k]
__device__ u64   g_Wp[980 * 64];         // Wf1 n-pairs: (Wf1[2np][k], Wf1[2np+1][k])
__device__ float g_P[14 * NB * 128];     // split-K partial H (n padded to 128)

// ---- packed f32x2 helpers ----
__device__ __forceinline__ u64 splat2(float a){
    u64 r; asm("mov.b64 %0, {%1, %1};" : "=l"(r) : "f"(a)); return r;
}
__device__ __forceinline__ u64 pack2(float a, float b){
    u64 r; asm("mov.b64 %0, {%1, %2};" : "=l"(r) : "f"(a), "f"(b)); return r;
}
__device__ __forceinline__ void unpack2(u64 v, float &x, float &y){
    asm("mov.b64 {%0, %1}, %2;" : "=f"(x), "=f"(y) : "l"(v));
}
__device__ __forceinline__ u64 fma2(u64 a, u64 b, u64 c){
    u64 d; asm("fma.rn.f32x2 %0, %1, %2, %3;" : "=l"(d) : "l"(a), "l"(b), "l"(c));
    return d;
}

// ===========================================================================
// kT: g_Wp[k][np] = (Wf1[2np][k], Wf1[2np+1][k])
// ===========================================================================
__global__ void __launch_bounds__(256)
kT(const float* __restrict__ Wf1)
{
    int idx = blockIdx.x * 256 + threadIdx.x;
    if (idx < 980 * 64) {
        int k = idx >> 6, np = idx & 63;
        int n0 = 2 * np;
        float w0 = (n0     < 100) ? Wf1[n0 * 980 + k]       : 0.f;
        float w1 = (n0 + 1 < 100) ? Wf1[(n0 + 1) * 980 + k] : 0.f;
        g_Wp[idx] = pack2(w0, w1);
    }
}

// ===========================================================================
// K1: fused conv stack. 2 samples/block, 288 threads.
// conv2 split into 280 tasks (sp, ocp, py, px-half) for 9-warp parallelism.
// ===========================================================================
#define K1_SMEM 58280

// Compute NOX output pre-pool columns starting at OX0 for one (ocp, py) pair.
template<int NOX, int OX0>
__device__ __forceinline__ void conv2_half(const float* pbase, const u64* wq,
                                           u64 acc[2][8])
{
    for (int ic = 0; ic < 10; ic++) {
        u64 w[9];
        #pragma unroll
        for (int k = 0; k < 9; k++) w[k] = wq[ic * 9 + k];
        const float* prow = pbase + ic * 544;
        #pragma unroll
        for (int rr = 0; rr < 4; rr++) {
            u64 ar[NOX + 2];
            #pragma unroll
            for (int c = 0; c < NOX + 2; c++)
                ar[c] = *(const u64*)(prow + rr * 34 + 2 * (OX0 + c));
            #pragma unroll
            for (int pr = 0; pr < 2; pr++) {
                int ky = rr - pr;
                if (ky >= 0 && ky <= 2) {
                    #pragma unroll
                    for (int kx = 0; kx < 3; kx++) {
                        u64 wv = w[ky * 3 + kx];
                        #pragma unroll
                        for (int j = 0; j < NOX; j++)
                            acc[pr][j] = fma2(ar[j + kx], wv, acc[pr][j]);
                    }
                }
            }
        }
    }
}

__global__ void __launch_bounds__(288)
k1_conv(const float* __restrict__ x, const float* __restrict__ Wc1,
        const float* __restrict__ Wc2)
{
    extern __shared__ char smraw[];
    float* xs  = (float*)(smraw);            // [2][30][30]
    u64*   w1p = (u64*)  (smraw + 7200);     // [5 ocp][9]
    u64*   w2p = (u64*)  (smraw + 7560);     // [10 ocp][90]
    float* p1s = (float*)(smraw + 14760);    // [2][10][16][34] (dup pairs)

    const int tid = threadIdx.x;
    const int s0  = blockIdx.x * 2;

    for (int i = tid; i < 1800; i += 288) {
        int sp = i / 900, e = i - sp * 900;
        int r = e / 30, c = e - r * 30;
        float v = 0.f;
        if (r >= 1 && r <= 28 && c >= 1 && c <= 28)
            v = x[(s0 + sp) * 784 + (r - 1) * 28 + (c - 1)];
        xs[i] = v;
    }
    if (tid < 45) {
        int cp = tid / 9, k = tid - cp * 9;
        w1p[tid] = pack2(Wc1[(2 * cp) * 9 + k], Wc1[(2 * cp + 1) * 9 + k]);
    }
    for (int i = tid; i < 900; i += 288) {
        int ocp = i / 90, t = i - ocp * 90;
        w2p[i] = pack2(Wc2[(2 * ocp) * 90 + t], Wc2[(2 * ocp + 1) * 90 + t]);
    }
    for (int i = tid; i < 10880; i += 288) p1s[i] = 0.f;
    __syncthreads();

    // ---- conv1 + spike + pool : tasks (sp, ocp=5, pos=196) = 1960 ----
    for (int task = tid; task < 1960; task += 288) {
        int sp  = task / 980;
        int r   = task - sp * 980;
        int cp  = r / 196;
        int pos = r - cp * 196;
        int py = pos / 14, px = pos - py * 14;
        const float* xb = xs + sp * 900 + (2 * py) * 30 + 2 * px;
        u64 acc[2][2];
        acc[0][0] = acc[0][1] = acc[1][0] = acc[1][1] = 0ull;
        #pragma unroll
        for (int rr = 0; rr < 4; rr++) {
            u64 cc[4];
            #pragma unroll
            for (int c = 0; c < 4; c++) cc[c] = splat2(xb[rr * 30 + c]);
            #pragma unroll
            for (int dy = 0; dy < 2; dy++) {
                int ky = rr - dy;
                if (ky >= 0 && ky <= 2) {
                    #pragma unroll
                    for (int kx = 0; kx < 3; kx++) {
                        u64 w = w1p[cp * 9 + ky * 3 + kx];
                        acc[dy][0] = fma2(cc[kx],     w, acc[dy][0]);
                        acc[dy][1] = fma2(cc[kx + 1], w, acc[dy][1]);
                    }
                }
            }
        }
        float f0 = 0.f, f1 = 0.f, lo, hi;
        #pragma unroll
        for (int dy = 0; dy < 2; dy++)
            #pragma unroll
            for (int dx = 0; dx < 2; dx++) {
                unpack2(acc[dy][dx], lo, hi);
                if (lo >= 1.f) f0 = 1.f;
                if (hi >= 1.f) f1 = 1.f;
            }
        int base = ((sp * 10 + 2 * cp) * 16 + (py + 1)) * 34 + 2 * (px + 1);
        p1s[base]       = f0; p1s[base + 1]   = f0;
        p1s[base + 544] = f1; p1s[base + 545] = f1;
    }
    __syncthreads();

    // ---- conv2 + spike + pool : tasks (sp, ocp=10, py=7, half=2) = 280 ----
    if (tid < 280) {
        int sp   = tid / 140;
        int r    = tid - sp * 140;
        int ocp  = r / 14;
        int q    = r - ocp * 14;
        int py   = q >> 1, half = q & 1;

        u64 acc[2][8];
        #pragma unroll
        for (int i = 0; i < 2; i++)
            #pragma unroll
            for (int j = 0; j < 8; j++) acc[i][j] = 0ull;

        const float* pbase = p1s + sp * 5440 + (2 * py) * 34;
        const u64*   wq    = w2p + ocp * 90;

        if (half == 0) conv2_half<8, 0>(pbase, wq, acc);
        else           conv2_half<6, 8>(pbase, wq, acc);

        int s = s0 + sp;
        float* z0 = g_Z + s * 980 + (2 * ocp) * 49 + py * 7 + (half ? 4 : 0);
        int npx = half ? 3 : 4;
        for (int jj = 0; jj < npx; jj++) {
            float a, b, c, d, e, f, g, h;
            unpack2(acc[0][2 * jj],     a, b);
            unpack2(acc[0][2 * jj + 1], c, d);
            unpack2(acc[1][2 * jj],     e, f);
            unpack2(acc[1][2 * jj + 1], g, h);
            z0[jj]      = (a >= 1.f || c >= 1.f || e >= 1.f || g >= 1.f) ? 1.f : 0.f;
            z0[49 + jj] = (b >= 1.f || d >= 1.f || f >= 1.f || h >= 1.f) ? 1.f : 0.f;
        }
    }
}

// ===========================================================================
// K2: split-K GEMM, n-pair weights + duplicated Z pairs. grid (64, 14), 256 thr.
// BM=64, seg=70 k (2 chunks of 35). Thread (tx,ty): m = ty+16i (i<4),
// n-pair = tx+16j (j<4). Per k: 4 LDS64 z + 4 LDS64 w + 16 fma2.
// ===========================================================================
#define K2_SMEM (18208 + 35*64*8)   // Zs[35][130] f (18200->18208) + Ws[35][64] u64

__global__ void __launch_bounds__(256)
k2_gemm()
{
    extern __shared__ char smraw[];
    float* Zs = (float*)smraw;              // [35][130] duplicated pairs
    u64*   Ws = (u64*)(smraw + 18208);      // [35][64]

    const int tid = threadIdx.x;
    const int tx  = tid & 15, ty = tid >> 4;
    const int m0  = blockIdx.x * 64;
    const int k0  = blockIdx.y * 70;

    u64 acc[4][4];
    #pragma unroll
    for (int i = 0; i < 4; i++)
        #pragma unroll
        for (int j = 0; j < 4; j++) acc[i][j] = 0ull;

    for (int c0 = 0; c0 < 70; c0 += 35) {
        __syncthreads();
        for (int e = tid; e < 2240; e += 256) {
            int m = e / 35, k = e - m * 35;
            float v = g_Z[(m0 + m) * 980 + k0 + c0 + k];
            *(u64*)(Zs + k * 130 + 2 * m) = pack2(v, v);
        }
        for (int e = tid; e < 2240; e += 256) {
            int k = e >> 6, np = e & 63;
            Ws[e] = g_Wp[(k0 + c0 + k) * 64 + np];
        }
        __syncthreads();
        #pragma unroll 7
        for (int k = 0; k < 35; k++) {
            u64 zz[4];
            #pragma unroll
            for (int i = 0; i < 4; i++)
                zz[i] = *(const u64*)(Zs + k * 130 + 2 * (ty + 16 * i));
            #pragma unroll
            for (int j = 0; j < 4; j++) {
                u64 w = Ws[k * 64 + tx + 16 * j];
                #pragma unroll
                for (int i = 0; i < 4; i++)
                    acc[i][j] = fma2(zz[i], w, acc[i][j]);
            }
        }
    }

    u64* p = (u64*)g_P + blockIdx.y * (NB * 64);
    #pragma unroll
    for (int i = 0; i < 4; i++) {
        int m = m0 + ty + 16 * i;
        #pragma unroll
        for (int j = 0; j < 4; j++)
            p[m * 64 + tx + 16 * j] = acc[i][j];
    }
}

// ===========================================================================
// K3: one warp per sample. grid 512, block 256 (8 warps = 8 samples).
// ===========================================================================
__device__ __forceinline__ uint32 lifmask(float h){
    float v = 0.f; uint32 m = 0u;
    #pragma unroll
    for (int t = 0; t < 32; t++) {
        v += (h - v) * 0.5f;
        if (v >= 1.f) { m |= (1u << t); v = 0.f; }
    }
    return m;
}

__global__ void __launch_bounds__(256)
k3_lif(const float* __restrict__ Wf2, float* __restrict__ out)
{
    __shared__ u64    W2p[500];          // i-pairs: (Wf2[2p][j], Wf2[2p+1][j])
    __shared__ uint32 Msk[8 * 100];
    __shared__ float  ysm[8 * 320];
    __shared__ float  cs[8 * 16];

    const int tid  = threadIdx.x;
    const int wid  = tid >> 5, lane = tid & 31;
    const int m    = blockIdx.x * 8 + wid;

    for (int e = tid; e < 500; e += 256) {
        int p = e / 100, j = e - p * 100;
        W2p[e] = pack2(Wf2[(2 * p) * 100 + j], Wf2[(2 * p + 1) * 100 + j]);
    }
    __syncthreads();

    // Phase A+B: sum 14 split-K partials, LIF-1 masks
    #pragma unroll
    for (int q = 0; q < 4; q++) {
        int n = q * 32 + lane;
        if (n < 100) {
            int idx = m * 128 + n;
            float h = 0.f;
            #pragma unroll
            for (int s = 0; s < 14; s++) h += g_P[s * (NB * 128) + idx];
            Msk[wid * 100 + n] = lifmask(h);
        }
    }
    __syncwarp();

    // Phase C: lane = timestep t; y[i] via i-paired fma2
    {
        u64 y[5];
        #pragma unroll
        for (int p = 0; p < 5; p++) y[p] = 0ull;
        const uint32* mk = Msk + wid * 100;
        #pragma unroll 4
        for (int j = 0; j < 100; j++) {
            u64 b = splat2((float)((mk[j] >> lane) & 1u));
            #pragma unroll
            for (int p = 0; p < 5; p++)
                y[p] = fma2(b, W2p[p * 100 + j], y[p]);
        }
        float* yr = ysm + wid * 320 + lane * 10;
        #pragma unroll
        for (int p = 0; p < 5; p++) {
            float a, bb; unpack2(y[p], a, bb);
            yr[2 * p] = a; yr[2 * p + 1] = bb;
        }
    }
    __syncwarp();

    // Phase D: v2 LIF + softmax
    if (lane < 10) {
        float v = 0.f, cnt = 0.f;
        const float* yr = ysm + wid * 320;
        #pragma unroll
        for (int t = 0; t < 32; t++) {
            float yv = yr[t * 10 + lane];
            v += (yv - v) * 0.5f;
            if (v >= 1.f) { cnt += 1.f; v = 0.f; }
        }
        cs[wid * 16 + lane] = cnt * (1.f / 32.f);
    }
    __syncwarp();
    if (lane < 10) {
        const float* c = cs + wid * 16;
        float mx = -1e30f;
        #pragma unroll
        for (int q = 0; q < 10; q++) mx = fmaxf(mx, c[q]);
        float sum = 0.f;
        #pragma unroll
        for (int q = 0; q < 10; q++) sum += expf(c[q] - mx);
        out[m * 10 + lane] = expf(c[lane] - mx) / sum;
    }
}

// ===========================================================================
extern "C" void kernel_launch(void* const* d_in, const int* in_sizes, int n_in,
                              void* d_out, int out_size)
{
    const float* x   = (const float*)d_in[0];
    const float* Wc1 = (const float*)d_in[1];
    const float* Wc2 = (const float*)d_in[2];
    const float* Wf1 = (const float*)d_in[3];
    const float* Wf2 = (const float*)d_in[4];
    float* out = (float*)d_out;

    cudaFuncSetAttribute(k1_conv, cudaFuncAttributeMaxDynamicSharedMemorySize, K1_SMEM);
    cudaFuncSetAttribute(k2_gemm, cudaFuncAttributeMaxDynamicSharedMemorySize, K2_SMEM);

    kT<<<(980 * 64 + 255) / 256, 256>>>(Wf1);
    k1_conv<<<NB / 2, 288, K1_SMEM>>>(x, Wc1, Wc2);
    dim3 g2(64, 14);
    k2_gemm<<<g2, 256, K2_SMEM>>>();
    k3_lif<<<NB / 8, 256>>>(Wf2, out);
}

// round 10
// speedup vs baseline: 1.2552x; 1.2552x over previous
#include <cuda_runtime.h>
#include <math.h>

// Spiking CNN forward, B=4096.

#define NB 4096
typedef unsigned long long u64;
typedef unsigned int uint32;

__device__ float g_Z[NB * 980];          // binary conv-stack output [m][k]
__device__ u64   g_Wp[980 * 64];         // Wf1 n-pairs: (Wf1[2np][k], Wf1[2np+1][k])
__device__ float g_P[7 * NB * 128];      // split-K partial H (n padded to 128)

// ---- packed f32x2 helpers ----
__device__ __forceinline__ u64 splat2(float a){
    u64 r; asm("mov.b64 %0, {%1, %1};" : "=l"(r) : "f"(a)); return r;
}
__device__ __forceinline__ u64 pack2(float a, float b){
    u64 r; asm("mov.b64 %0, {%1, %2};" : "=l"(r) : "f"(a), "f"(b)); return r;
}
__device__ __forceinline__ void unpack2(u64 v, float &x, float &y){
    asm("mov.b64 {%0, %1}, %2;" : "=f"(x), "=f"(y) : "l"(v));
}
__device__ __forceinline__ u64 fma2(u64 a, u64 b, u64 c){
    u64 d; asm("fma.rn.f32x2 %0, %1, %2, %3;" : "=l"(d) : "l"(a), "l"(b), "l"(c));
    return d;
}

// ===========================================================================
// kT: g_Wp[k][np] = (Wf1[2np][k], Wf1[2np+1][k])
// ===========================================================================
__global__ void __launch_bounds__(256)
kT(const float* __restrict__ Wf1)
{
    int idx = blockIdx.x * 256 + threadIdx.x;
    if (idx < 980 * 64) {
        int k = idx >> 6, np = idx & 63;
        int n0 = 2 * np;
        float w0 = (n0     < 100) ? Wf1[n0 * 980 + k]       : 0.f;
        float w1 = (n0 + 1 < 100) ? Wf1[(n0 + 1) * 980 + k] : 0.f;
        g_Wp[idx] = pack2(w0, w1);
    }
}

// ===========================================================================
// K1: fused conv stack (R8 version: 160 threads, unsplit conv2)
// ===========================================================================
#define K1_SMEM 58280

__global__ void __launch_bounds__(160)
k1_conv(const float* __restrict__ x, const float* __restrict__ Wc1,
        const float* __restrict__ Wc2)
{
    extern __shared__ char smraw[];
    float* xs  = (float*)(smraw);            // [2][30][30]
    u64*   w1p = (u64*)  (smraw + 7200);     // [5 ocp][9]
    u64*   w2p = (u64*)  (smraw + 7560);     // [10 ocp][90]
    float* p1s = (float*)(smraw + 14760);    // [2][10][16][34]

    const int tid = threadIdx.x;
    const int s0  = blockIdx.x * 2;

    for (int i = tid; i < 1800; i += 160) {
        int sp = i / 900, e = i - sp * 900;
        int r = e / 30, c = e - r * 30;
        float v = 0.f;
        if (r >= 1 && r <= 28 && c >= 1 && c <= 28)
            v = x[(s0 + sp) * 784 + (r - 1) * 28 + (c - 1)];
        xs[i] = v;
    }
    if (tid < 45) {
        int cp = tid / 9, k = tid - cp * 9;
        w1p[tid] = pack2(Wc1[(2 * cp) * 9 + k], Wc1[(2 * cp + 1) * 9 + k]);
    }
    for (int i = tid; i < 900; i += 160) {
        int ocp = i / 90, t = i - ocp * 90;
        w2p[i] = pack2(Wc2[(2 * ocp) * 90 + t], Wc2[(2 * ocp + 1) * 90 + t]);
    }
    for (int i = tid; i < 10880; i += 160) p1s[i] = 0.f;
    __syncthreads();

    for (int task = tid; task < 1960; task += 160) {
        int sp  = task / 980;
        int r   = task - sp * 980;
        int cp  = r / 196;
        int pos = r - cp * 196;
        int py = pos / 14, px = pos - py * 14;
        const float* xb = xs + sp * 900 + (2 * py) * 30 + 2 * px;
        u64 acc[2][2];
        acc[0][0] = acc[0][1] = acc[1][0] = acc[1][1] = 0ull;
        #pragma unroll
        for (int rr = 0; rr < 4; rr++) {
            u64 cc[4];
            #pragma unroll
            for (int c = 0; c < 4; c++) cc[c] = splat2(xb[rr * 30 + c]);
            #pragma unroll
            for (int dy = 0; dy < 2; dy++) {
                int ky = rr - dy;
                if (ky >= 0 && ky <= 2) {
                    #pragma unroll
                    for (int kx = 0; kx < 3; kx++) {
                        u64 w = w1p[cp * 9 + ky * 3 + kx];
                        acc[dy][0] = fma2(cc[kx],     w, acc[dy][0]);
                        acc[dy][1] = fma2(cc[kx + 1], w, acc[dy][1]);
                    }
                }
            }
        }
        float f0 = 0.f, f1 = 0.f, lo, hi;
        #pragma unroll
        for (int dy = 0; dy < 2; dy++)
            #pragma unroll
            for (int dx = 0; dx < 2; dx++) {
                unpack2(acc[dy][dx], lo, hi);
                if (lo >= 1.f) f0 = 1.f;
                if (hi >= 1.f) f1 = 1.f;
            }
        int base = ((sp * 10 + 2 * cp) * 16 + (py + 1)) * 34 + 2 * (px + 1);
        p1s[base]       = f0; p1s[base + 1]   = f0;
        p1s[base + 544] = f1; p1s[base + 545] = f1;
    }
    __syncthreads();

    if (tid < 140) {
        int sp  = tid / 70;
        int r70 = tid - sp * 70;
        int ocp = r70 / 7, py = r70 - ocp * 7;
        u64 acc[2][14];
        #pragma unroll
        for (int i = 0; i < 2; i++)
            #pragma unroll
            for (int j = 0; j < 14; j++) acc[i][j] = 0ull;

        const float* pbase = p1s + sp * 5440 + (2 * py) * 34;
        const u64*   wq    = w2p + ocp * 90;

        for (int ic = 0; ic < 10; ic++) {
            u64 w[9];
            #pragma unroll
            for (int k = 0; k < 9; k++) w[k] = wq[ic * 9 + k];
            const float* prow = pbase + ic * 544;
            #pragma unroll
            for (int rr = 0; rr < 4; rr++) {
                u64 arow[16];
                #pragma unroll
                for (int c = 0; c < 16; c++)
                    arow[c] = *(const u64*)(prow + rr * 34 + 2 * c);
                #pragma unroll
                for (int pr = 0; pr < 2; pr++) {
                    int ky = rr - pr;
                    if (ky >= 0 && ky <= 2) {
                        #pragma unroll
                        for (int kx = 0; kx < 3; kx++) {
                            u64 wv = w[ky * 3 + kx];
                            #pragma unroll
                            for (int ox = 0; ox < 14; ox++)
                                acc[pr][ox] = fma2(arow[ox + kx], wv, acc[pr][ox]);
                        }
                    }
                }
            }
        }
        int s = s0 + sp;
        float* z0 = g_Z + s * 980 + (2 * ocp) * 49 + py * 7;
        #pragma unroll
        for (int px = 0; px < 7; px++) {
            float a, b, c, d, e, f, g, h;
            unpack2(acc[0][2 * px],     a, b);
            unpack2(acc[0][2 * px + 1], c, d);
            unpack2(acc[1][2 * px],     e, f);
            unpack2(acc[1][2 * px + 1], g, h);
            z0[px]      = (a >= 1.f || c >= 1.f || e >= 1.f || g >= 1.f) ? 1.f : 0.f;
            z0[49 + px] = (b >= 1.f || d >= 1.f || f >= 1.f || h >= 1.f) ? 1.f : 0.f;
        }
    }
}

// ===========================================================================
// K2: split-K GEMM, n-pair weights + DUPLICATED Z pairs (only change vs R8).
// grid (64, 7), block 256. BM=64, seg=140 k (4 chunks of 35).
// Thread (tx,ty): m = ty+16i (i<4), n-pair = tx+16j (j<4).
// Per k: 4 LDS64 z + 4 LDS64 w + 16 fma2 (splats eliminated).
// ===========================================================================
#define K2_SMEM (18208 + 35*64*8)   // Zs[35][130] f + Ws[35][64] u64 = 36128

__global__ void __launch_bounds__(256)
k2_gemm()
{
    extern __shared__ char smraw[];
    float* Zs = (float*)smraw;              // [35][130] duplicated pairs
    u64*   Ws = (u64*)(smraw + 18208);      // [35][64]

    const int tid = threadIdx.x;
    const int tx  = tid & 15, ty = tid >> 4;
    const int m0  = blockIdx.x * 64;
    const int k0  = blockIdx.y * 140;

    u64 acc[4][4];
    #pragma unroll
    for (int i = 0; i < 4; i++)
        #pragma unroll
        for (int j = 0; j < 4; j++) acc[i][j] = 0ull;

    for (int c0 = 0; c0 < 140; c0 += 35) {
        __syncthreads();
        for (int e = tid; e < 2240; e += 256) {
            int m = e / 35, k = e - m * 35;
            float v = g_Z[(m0 + m) * 980 + k0 + c0 + k];
            *(u64*)(Zs + k * 130 + 2 * m) = pack2(v, v);
        }
        for (int e = tid; e < 2240; e += 256) {
            int k = e >> 6, np = e & 63;
            Ws[e] = g_Wp[(k0 + c0 + k) * 64 + np];
        }
        __syncthreads();
        #pragma unroll 5
        for (int k = 0; k < 35; k++) {
            u64 zz[4];
            #pragma unroll
            for (int i = 0; i < 4; i++)
                zz[i] = *(const u64*)(Zs + k * 130 + 2 * (ty + 16 * i));
            #pragma unroll
            for (int j = 0; j < 4; j++) {
                u64 w = Ws[k * 64 + tx + 16 * j];
                #pragma unroll
                for (int i = 0; i < 4; i++)
                    acc[i][j] = fma2(zz[i], w, acc[i][j]);
            }
        }
    }

    u64* p = (u64*)g_P + blockIdx.y * (NB * 64);
    #pragma unroll
    for (int i = 0; i < 4; i++) {
        int m = m0 + ty + 16 * i;
        #pragma unroll
        for (int j = 0; j < 4; j++)
            p[m * 64 + tx + 16 * j] = acc[i][j];
    }
}

// ===========================================================================
// K3: one warp per sample. grid 512, block 256 (8 warps = 8 samples).
// ===========================================================================
__device__ __forceinline__ uint32 lifmask(float h){
    float v = 0.f; uint32 m = 0u;
    #pragma unroll
    for (int t = 0; t < 32; t++) {
        v += (h - v) * 0.5f;
        if (v >= 1.f) { m |= (1u << t); v = 0.f; }
    }
    return m;
}

__global__ void __launch_bounds__(256)
k3_lif(const float* __restrict__ Wf2, float* __restrict__ out)
{
    __shared__ u64    W2p[500];          // i-pairs: (Wf2[2p][j], Wf2[2p+1][j])
    __shared__ uint32 Msk[8 * 100];
    __shared__ float  ysm[8 * 320];
    __shared__ float  cs[8 * 16];

    const int tid  = threadIdx.x;
    const int wid  = tid >> 5, lane = tid & 31;
    const int m    = blockIdx.x * 8 + wid;

    for (int e = tid; e < 500; e += 256) {
        int p = e / 100, j = e - p * 100;
        W2p[e] = pack2(Wf2[(2 * p) * 100 + j], Wf2[(2 * p + 1) * 100 + j]);
    }
    __syncthreads();

    // Phase A+B: sum 7 split-K partials, LIF-1 masks
    #pragma unroll
    for (int q = 0; q < 4; q++) {
        int n = q * 32 + lane;
        if (n < 100) {
            int idx = m * 128 + n;
            float h = 0.f;
            #pragma unroll
            for (int s = 0; s < 7; s++) h += g_P[s * (NB * 128) + idx];
            Msk[wid * 100 + n] = lifmask(h);
        }
    }
    __syncwarp();

    // Phase C: lane = timestep t; y[i] via i-paired fma2
    {
        u64 y[5];
        #pragma unroll
        for (int p = 0; p < 5; p++) y[p] = 0ull;
        const uint32* mk = Msk + wid * 100;
        #pragma unroll 4
        for (int j = 0; j < 100; j++) {
            u64 b = splat2((float)((mk[j] >> lane) & 1u));
            #pragma unroll
            for (int p = 0; p < 5; p++)
                y[p] = fma2(b, W2p[p * 100 + j], y[p]);
        }
        float* yr = ysm + wid * 320 + lane * 10;
        #pragma unroll
        for (int p = 0; p < 5; p++) {
            float a, bb; unpack2(y[p], a, bb);
            yr[2 * p] = a; yr[2 * p + 1] = bb;
        }
    }
    __syncwarp();

    // Phase D: v2 LIF + softmax
    if (lane < 10) {
        float v = 0.f, cnt = 0.f;
        const float* yr = ysm + wid * 320;
        #pragma unroll
        for (int t = 0; t < 32; t++) {
            float yv = yr[t * 10 + lane];
            v += (yv - v) * 0.5f;
            if (v >= 1.f) { cnt += 1.f; v = 0.f; }
        }
        cs[wid * 16 + lane] = cnt * (1.f / 32.f);
    }
    __syncwarp();
    if (lane < 10) {
        const float* c = cs + wid * 16;
        float mx = -1e30f;
        #pragma unroll
        for (int q = 0; q < 10; q++) mx = fmaxf(mx, c[q]);
        float sum = 0.f;
        #pragma unroll
        for (int q = 0; q < 10; q++) sum += expf(c[q] - mx);
        out[m * 10 + lane] = expf(c[lane] - mx) / sum;
    }
}

// ===========================================================================
extern "C" void kernel_launch(void* const* d_in, const int* in_sizes, int n_in,
                              void* d_out, int out_size)
{
    const float* x   = (const float*)d_in[0];
    const float* Wc1 = (const float*)d_in[1];
    const float* Wc2 = (const float*)d_in[2];
    const float* Wf1 = (const float*)d_in[3];
    const float* Wf2 = (const float*)d_in[4];
    float* out = (float*)d_out;

    cudaFuncSetAttribute(k1_conv, cudaFuncAttributeMaxDynamicSharedMemorySize, K1_SMEM);
    cudaFuncSetAttribute(k2_gemm, cudaFuncAttributeMaxDynamicSharedMemorySize, K2_SMEM);

    kT<<<(980 * 64 + 255) / 256, 256>>>(Wf1);
    k1_conv<<<NB / 2, 160, K1_SMEM>>>(x, Wc1, Wc2);
    dim3 g2(64, 7);
    k2_gemm<<<g2, 256, K2_SMEM>>>();
    k3_lif<<<NB / 8, 256>>>(Wf2, out);
}